// round 4
// baseline (speedup 1.0000x reference)
#include <cuda_runtime.h>

#define BB 512
#define LL 2048
#define CC 64
#define START_S 62
#define STOP_S 63

// scratch (no cudaMalloc allowed)
__device__ float g_expTt[CC * CC];     // [cprime][c] = exp(T[c][cprime])  (transposed)
__device__ float g_eTstop[CC];         // exp(T[c][STOP])
__device__ float g_trow_start[CC];     // T[START][cprime]
__device__ float g_part[BB];
__device__ float g_scores[BB];

typedef unsigned long long u64;

// packed fp32x2 ops (sm_100+ PTX only; ptxas never emits these from C++)
__device__ __forceinline__ u64 fma2(u64 a, u64 b, u64 c) {
    u64 d;
    asm("fma.rn.f32x2 %0, %1, %2, %3;" : "=l"(d) : "l"(a), "l"(b), "l"(c));
    return d;
}
__device__ __forceinline__ u64 fadd2(u64 a, u64 b) {
    u64 d;
    asm("add.rn.f32x2 %0, %1, %2;" : "=l"(d) : "l"(a), "l"(b));
    return d;
}
__device__ __forceinline__ float sum2(u64 a) {
    float lo, hi;
    asm("mov.b64 {%0,%1}, %2;" : "=f"(lo), "=f"(hi) : "l"(a));
    return lo + hi;
}

// ---------------------------------------------------------------------------
// Precompute exp(T) transposed + boundary vectors.
// ---------------------------------------------------------------------------
__global__ void prep_kernel(const float* __restrict__ T) {
    int i = blockIdx.x * blockDim.x + threadIdx.x;
    if (i < CC * CC) {
        int cp = i >> 6;
        int c  = i & 63;
        g_expTt[i] = __expf(T[c * CC + cp]);   // exp(-10000) -> 0, fine
    }
    if (i < CC) {
        g_eTstop[i]     = __expf(T[i * CC + STOP_S]);
        g_trow_start[i] = T[START_S * CC + i];
    }
}

// full 64-dot in packed fp32x2: 32 FFMA2, 4 chains of depth 8, packed combine
__device__ __forceinline__ float dot64(const float* __restrict__ vsrc,
                                       const u64* __restrict__ eT) {
    const ulonglong2* vp = reinterpret_cast<const ulonglong2*>(vsrc);
    u64 a0 = 0, a1 = 0, a2 = 0, a3 = 0;   // 0x0 == packed {0.f,0.f}
#pragma unroll
    for (int k = 0; k < 16; k += 2) {
        ulonglong2 v0 = vp[k];
        ulonglong2 v1 = vp[k + 1];
        a0 = fma2(v0.x, eT[2 * k + 0], a0);
        a1 = fma2(v0.y, eT[2 * k + 1], a1);
        a2 = fma2(v1.x, eT[2 * k + 2], a2);
        a3 = fma2(v1.y, eT[2 * k + 3], a3);
    }
    return sum2(fadd2(fadd2(a0, a1), fadd2(a2, a3)));
}

// ---------------------------------------------------------------------------
// Forward algorithm in exp-space, TWO batches per 64-thread CTA.
// Thread cp owns output state cp for both batches; the exp(T) column (32
// packed-b64 regs) is shared between the two independent recursions, which
// interleave to fill issue/latency gaps. One barrier per step covers both.
// Renormalization every 2 steps, pipelined OFF the critical chain:
//   odd step t : launch warp-max shuffles (concurrent with the dots)
//   even step  : fold r = 1/max into the emission factor, S += log(max)
// Invariant: alpha[c] = log(v[c]) + S, per batch.
// ---------------------------------------------------------------------------
__global__ void __launch_bounds__(CC) alpha_kernel(const float* __restrict__ em,
                                                   const float* __restrict__ mask) {
    const int b0   = blockIdx.x * 2;
    const int cp   = threadIdx.x;
    const int lane = cp & 31;
    const int wid  = cp >> 5;

    __shared__ __align__(16) float vsh[2][2][CC];   // [batch][buf][c]
    __shared__ float smax[2][2];                    // [batch][warp]
    __shared__ float ssum[2][2];

    // my exp(T) column, packed pairs (shared by both batches)
    u64 eT[32];
    {
        const ulonglong2* col = reinterpret_cast<const ulonglong2*>(&g_expTt[cp * CC]);
#pragma unroll
        for (int k = 0; k < 16; ++k) {
            ulonglong2 q = col[k];
            eT[2 * k + 0] = q.x;
            eT[2 * k + 1] = q.y;
        }
    }

    const float* emb0 = em + (size_t)b0 * (LL * CC);
    const float* emb1 = emb0 + (size_t)(LL * CC);
    const float* mkb0 = mask + (size_t)b0 * LL;
    const float* mkb1 = mkb0 + LL;

    // t = 0
    float ts = g_trow_start[cp];
    float v0 = __expf(emb0[cp] + ts);
    float v1 = __expf(emb1[cp] + ts);
    float S0 = 0.0f, S1 = 0.0f;
    vsh[0][0][cp] = v0;
    vsh[1][0][cp] = v1;

    // prefetch pipeline, distance 2 (both batches)
    float ea0 = emb0[CC + cp],     ea1 = emb1[CC + cp];
    float ma0 = mkb0[1],           ma1 = mkb1[1];
    float eb0 = emb0[2 * CC + cp], eb1 = emb1[2 * CC + cp];
    float mb0 = mkb0[2],           mb1 = mkb1[2];

    __syncthreads();

    int cur = 0;
#pragma unroll 1
    for (int t = 1; t + 1 < LL; t += 2) {
        // ============ odd step t: launch the max-reduces ============
        {
            size_t off = (size_t)(t + 2) * CC + cp;
            float en0 = emb0[off], en1 = emb1[off];
            float mn0 = mkb0[t + 2], mn1 = mkb1[t + 2];

            // warp maxes of previous v's — independent of the dots below
            float x0 = v0, x1 = v1;
#pragma unroll
            for (int o = 16; o; o >>= 1) {
                x0 = fmaxf(x0, __shfl_xor_sync(0xffffffffu, x0, o));
                x1 = fmaxf(x1, __shfl_xor_sync(0xffffffffu, x1, o));
            }
            if (lane == 0) { smax[0][wid] = x0; smax[1][wid] = x1; }

            float ee0 = __expf(ea0);
            float ee1 = __expf(ea1);
            float a0  = dot64(vsh[0][cur], eT);
            float a1  = dot64(vsh[1][cur], eT);
            float nv0 = (ma0 > 0.f) ? a0 * ee0 : v0;
            float nv1 = (ma1 > 0.f) ? a1 * ee1 : v1;
            v0 = nv0; v1 = nv1;
            vsh[0][cur ^ 1][cp] = nv0;
            vsh[1][cur ^ 1][cp] = nv1;
            __syncthreads();
            cur ^= 1;
            ea0 = eb0; ma0 = mb0; eb0 = en0; mb0 = mn0;
            ea1 = eb1; ma1 = mb1; eb1 = en1; mb1 = mn1;
        }
        // ============ even step t+1: apply renorm ============
        {
            int tp = t + 3;
            if (tp > LL - 1) tp = LL - 1;
            size_t off = (size_t)tp * CC + cp;
            float en0 = emb0[off], en1 = emb1[off];
            float mn0 = mkb0[tp], mn1 = mkb1[tp];

            float m0 = fmaxf(smax[0][0], smax[0][1]);
            float m1 = fmaxf(smax[1][0], smax[1][1]);
            float r0 = __fdividef(1.0f, m0);
            float r1 = __fdividef(1.0f, m1);
            S0 += __logf(m0);
            S1 += __logf(m1);

            float ee0 = __expf(ea0) * r0;
            float ee1 = __expf(ea1) * r1;
            float a0  = dot64(vsh[0][cur], eT);
            float a1  = dot64(vsh[1][cur], eT);
            float nv0 = (ma0 > 0.f) ? a0 * ee0 : v0 * r0;
            float nv1 = (ma1 > 0.f) ? a1 * ee1 : v1 * r1;
            v0 = nv0; v1 = nv1;
            vsh[0][cur ^ 1][cp] = nv0;
            vsh[1][cur ^ 1][cp] = nv1;
            __syncthreads();
            cur ^= 1;
            ea0 = eb0; ma0 = mb0; eb0 = en0; mb0 = mn0;
            ea1 = eb1; ma1 = mb1; eb1 = en1; mb1 = mn1;
        }
    }
    // tail step t = LL-1 (odd)
    {
        float ee0 = __expf(ea0);
        float ee1 = __expf(ea1);
        float a0  = dot64(vsh[0][cur], eT);
        float a1  = dot64(vsh[1][cur], eT);
        v0 = (ma0 > 0.f) ? a0 * ee0 : v0;
        v1 = (ma1 > 0.f) ? a1 * ee1 : v1;
    }

    // partition_b = log( sum_c v[c] * exp(T[c,STOP]) ) + S
    float es = g_eTstop[cp];
    float t0 = v0 * es;
    float t1 = v1 * es;
#pragma unroll
    for (int o = 16; o; o >>= 1) {
        t0 += __shfl_xor_sync(0xffffffffu, t0, o);
        t1 += __shfl_xor_sync(0xffffffffu, t1, o);
    }
    if (lane == 0) { ssum[0][wid] = t0; ssum[1][wid] = t1; }
    __syncthreads();
    if (cp == 0) g_part[b0]     = __logf(ssum[0][0] + ssum[0][1]) + S0;
    if (cp == 1) g_part[b0 + 1] = __logf(ssum[1][0] + ssum[1][1]) + S1;
}

// ---------------------------------------------------------------------------
// Gold path score per batch (cheap gathers).
// ---------------------------------------------------------------------------
__global__ void __launch_bounds__(256) scores_kernel(const float* __restrict__ em,
                                                     const float* __restrict__ T,
                                                     const float* __restrict__ mask,
                                                     const int* __restrict__ tags) {
    const int b   = blockIdx.x;
    const int tid = threadIdx.x;
    const float* emb = em + (size_t)b * (LL * CC);
    const float* mkb = mask + (size_t)b * LL;
    const int*   tgb = tags + (size_t)b * LL;

    float acc = 0.f, msum = 0.f;
    for (int t = tid; t < LL; t += 256) {
        msum += mkb[t];
        if (t >= 1) {
            int tg = tgb[t];
            int tq = tgb[t - 1];
            acc += (emb[(size_t)t * CC + tg] + T[tq * CC + tg]) * mkb[t];
        }
    }

    __shared__ float sacc[8], smsum[8];
#pragma unroll
    for (int o = 16; o; o >>= 1) {
        acc  += __shfl_xor_sync(0xffffffffu, acc, o);
        msum += __shfl_xor_sync(0xffffffffu, msum, o);
    }
    int lane = tid & 31, w = tid >> 5;
    if (lane == 0) { sacc[w] = acc; smsum[w] = msum; }
    __syncthreads();
    if (tid == 0) {
        float A = 0.f, M = 0.f;
#pragma unroll
        for (int i = 0; i < 8; ++i) { A += sacc[i]; M += smsum[i]; }
        int t0 = tgb[0];
        float s = A + emb[t0] + T[START_S * CC + t0];
        int last = (int)M - 1;               // mask sum of 1.0s is exact in fp32
        s += T[tgb[last] * CC + STOP_S];
        g_scores[b] = s;
    }
}

// ---------------------------------------------------------------------------
// mean(partition - scores)
// ---------------------------------------------------------------------------
__global__ void __launch_bounds__(512) finalize_kernel(float* __restrict__ out) {
    int tid = threadIdx.x;
    float d = g_part[tid] - g_scores[tid];
    __shared__ float sh[16];
#pragma unroll
    for (int o = 16; o; o >>= 1) d += __shfl_xor_sync(0xffffffffu, d, o);
    if ((tid & 31) == 0) sh[tid >> 5] = d;
    __syncthreads();
    if (tid < 16) {
        float x = sh[tid];
#pragma unroll
        for (int o = 8; o; o >>= 1) x += __shfl_xor_sync(0x0000ffffu, x, o);
        if (tid == 0) out[0] = x * (1.0f / BB);
    }
}

extern "C" void kernel_launch(void* const* d_in, const int* in_sizes, int n_in,
                              void* d_out, int out_size) {
    (void)in_sizes; (void)n_in; (void)out_size;
    const float* em   = (const float*)d_in[0];
    const float* T    = (const float*)d_in[1];
    const float* mask = (const float*)d_in[2];
    const int*   tags = (const int*)d_in[3];
    float* out = (float*)d_out;

    // order: prep, alpha, scores, finalize — puts alpha at ncu's -s 5 window
    prep_kernel<<<8, 512>>>(T);
    alpha_kernel<<<BB / 2, CC>>>(em, mask);
    scores_kernel<<<BB, 256>>>(em, T, mask, tags);
    finalize_kernel<<<1, 512>>>(out);
}

// round 5
// speedup vs baseline: 1.2943x; 1.2943x over previous
#include <cuda_runtime.h>

#define BB 512
#define LL 2048
#define CC 64
#define START_S 62
#define STOP_S 63

// scratch (no cudaMalloc allowed)
__device__ float2 g_eT2[CC * 32];   // [k][j] = { exp(T[k][j]), exp(T[k][j+32]) }
__device__ float2 g_stop2[32];      // [j] = { exp(T[j][STOP]), exp(T[j+32][STOP]) }
__device__ float2 g_start2[32];     // [j] = { T[START][j], T[START][j+32] }
__device__ float g_part[BB];
__device__ float g_scores[BB];

typedef unsigned long long u64;

// packed fp32x2 ops (sm_100+ PTX only; ptxas never emits these from C++)
__device__ __forceinline__ u64 fma2(u64 a, u64 b, u64 c) {
    u64 d;
    asm("fma.rn.f32x2 %0, %1, %2, %3;" : "=l"(d) : "l"(a), "l"(b), "l"(c));
    return d;
}
__device__ __forceinline__ u64 fadd2(u64 a, u64 b) {
    u64 d;
    asm("add.rn.f32x2 %0, %1, %2;" : "=l"(d) : "l"(a), "l"(b));
    return d;
}
__device__ __forceinline__ u64 fmul2(u64 a, u64 b) {
    u64 d;
    asm("mul.rn.f32x2 %0, %1, %2;" : "=l"(d) : "l"(a), "l"(b));
    return d;
}
__device__ __forceinline__ u64 pack2(float lo, float hi) {
    u64 d;
    asm("mov.b64 %0, {%1,%2};" : "=l"(d) : "f"(lo), "f"(hi));
    return d;
}
__device__ __forceinline__ float lo2(u64 a) {
    float lo, hi;
    asm("mov.b64 {%0,%1}, %2;" : "=f"(lo), "=f"(hi) : "l"(a));
    return lo;
}
__device__ __forceinline__ float hi2(u64 a) {
    float lo, hi;
    asm("mov.b64 {%0,%1}, %2;" : "=f"(lo), "=f"(hi) : "l"(a));
    return hi;
}

// ---------------------------------------------------------------------------
// Precompute packed exp(T) + boundary vectors.
// ---------------------------------------------------------------------------
__global__ void prep_kernel(const float* __restrict__ T) {
    int i = blockIdx.x * blockDim.x + threadIdx.x;
    if (i < CC * 32) {
        int k = i >> 5;
        int j = i & 31;
        g_eT2[i] = make_float2(__expf(T[k * CC + j]), __expf(T[k * CC + j + 32]));
    }
    if (i < 32) {
        g_stop2[i]  = make_float2(__expf(T[i * CC + STOP_S]),
                                  __expf(T[(i + 32) * CC + STOP_S]));
        g_start2[i] = make_float2(T[START_S * CC + i], T[START_S * CC + i + 32]);
    }
}

// dual-state 64-dot: lane accumulates states (lane, lane+32) in the two fp32
// lanes of packed b64. 64 fma2, 4 chains of depth 16.
__device__ __forceinline__ u64 dot2x64(const float2* __restrict__ vdup,
                                       const u64* __restrict__ eT) {
    const ulonglong2* vp = reinterpret_cast<const ulonglong2*>(vdup);
    u64 a0 = 0, a1 = 0, a2 = 0, a3 = 0;   // 0x0 == packed {0.f,0.f}
#pragma unroll
    for (int k = 0; k < 32; k += 2) {
        ulonglong2 q0 = vp[k];
        ulonglong2 q1 = vp[k + 1];
        a0 = fma2(q0.x, eT[2 * k + 0], a0);
        a1 = fma2(q0.y, eT[2 * k + 1], a1);
        a2 = fma2(q1.x, eT[2 * k + 2], a2);
        a3 = fma2(q1.y, eT[2 * k + 3], a3);
    }
    return fadd2(fadd2(a0, a1), fadd2(a2, a3));
}

// ---------------------------------------------------------------------------
// Forward algorithm in exp-space. ONE WARP per batch — no __syncthreads, no
// cross-warp traffic. Lane owns states (lane, lane+32) packed in fp32x2.
// exp(T) columns for both states live in 64 packed b64 registers.
// v is exchanged through per-warp shared memory as duplicated pairs {v,v}
// (so the dot reads broadcast LDS.128 of ready-packed operands), guarded by
// __syncwarp only. Renorm every 2 steps: warp-max shuffles launch on the odd
// step (overlapping the dot), r=1/m is folded into the even step's emission.
// Invariant: alpha[c] = log(v[c]) + S.
// ---------------------------------------------------------------------------
__global__ void __launch_bounds__(128, 1) alpha_kernel(const float* __restrict__ em,
                                                       const float* __restrict__ mask) {
    const int wid  = threadIdx.x >> 5;
    const int lane = threadIdx.x & 31;
    const int b    = blockIdx.x * 4 + wid;

    __shared__ __align__(16) float2 vsh[4][2][CC];   // [warp][buf][state] dup pairs
    float2 (*vb)[CC] = vsh[wid];

    // my two exp(T) columns, packed: eT[k] = {expT[k][lane], expT[k][lane+32]}
    u64 eT[CC];
    {
        const u64* g = reinterpret_cast<const u64*>(g_eT2);
#pragma unroll
        for (int k = 0; k < CC; ++k) eT[k] = g[k * 32 + lane];   // coalesced LDG.64
    }

    const float* emb = em + (size_t)b * (LL * CC);
    const float* mkb = mask + (size_t)b * LL;

    // t = 0
    float2 st = g_start2[lane];
    float v0 = __expf(emb[lane] + st.x);
    float v1 = __expf(emb[lane + 32] + st.y);
    u64 v = pack2(v0, v1);
    float S = 0.0f;
    vb[0][lane]      = make_float2(v0, v0);
    vb[0][lane + 32] = make_float2(v1, v1);

    // prefetch pipeline, distance 3
    float Ae0 = emb[CC + lane],     Ae1 = emb[CC + lane + 32],     Amk = mkb[1];
    float Be0 = emb[2 * CC + lane], Be1 = emb[2 * CC + lane + 32], Bmk = mkb[2];
    float Ce0 = emb[3 * CC + lane], Ce1 = emb[3 * CC + lane + 32], Cmk = mkb[3];

    __syncwarp();

    int cur = 0;
    float mx = 0.0f;
#pragma unroll 1
    for (int t = 1; t + 1 < LL; t += 2) {
        // ============ odd step t: launch warp-max, plain step ============
        {
            int ti = t + 3;
            if (ti > LL - 1) ti = LL - 1;
            float ne0 = emb[(size_t)ti * CC + lane];
            float ne1 = emb[(size_t)ti * CC + lane + 32];
            float nmk = mkb[ti];

            // warp-max of previous v (both packed halves) — overlaps the dot
            float x = fmaxf(lo2(v), hi2(v));
#pragma unroll
            for (int o = 16; o; o >>= 1) x = fmaxf(x, __shfl_xor_sync(0xffffffffu, x, o));
            mx = x;

            u64 ee = pack2(__expf(Ae0), __expf(Ae1));
            u64 s  = dot2x64(vb[cur], eT);
            u64 nv = (Amk > 0.f) ? fmul2(s, ee) : v;
            v = nv;
            float l = lo2(nv), h = hi2(nv);
            vb[cur ^ 1][lane]      = make_float2(l, l);
            vb[cur ^ 1][lane + 32] = make_float2(h, h);
            __syncwarp();
            cur ^= 1;
            Ae0 = Be0; Ae1 = Be1; Amk = Bmk;
            Be0 = Ce0; Be1 = Ce1; Bmk = Cmk;
            Ce0 = ne0; Ce1 = ne1; Cmk = nmk;
        }
        // ============ even step t+1: apply renorm ============
        {
            int ti = t + 4;
            if (ti > LL - 1) ti = LL - 1;
            float ne0 = emb[(size_t)ti * CC + lane];
            float ne1 = emb[(size_t)ti * CC + lane + 32];
            float nmk = mkb[ti];

            float r = __fdividef(1.0f, mx);
            S += __logf(mx);
            u64 rp = pack2(r, r);

            u64 ee = fmul2(pack2(__expf(Ae0), __expf(Ae1)), rp);
            u64 s  = dot2x64(vb[cur], eT);
            u64 nv = (Amk > 0.f) ? fmul2(s, ee) : fmul2(v, rp);
            v = nv;
            float l = lo2(nv), h = hi2(nv);
            vb[cur ^ 1][lane]      = make_float2(l, l);
            vb[cur ^ 1][lane + 32] = make_float2(h, h);
            __syncwarp();
            cur ^= 1;
            Ae0 = Be0; Ae1 = Be1; Amk = Bmk;
            Be0 = Ce0; Be1 = Ce1; Bmk = Cmk;
            Ce0 = ne0; Ce1 = ne1; Cmk = nmk;
        }
    }
    // tail step t = LL-1 (odd)
    {
        u64 ee = pack2(__expf(Ae0), __expf(Ae1));
        u64 s  = dot2x64(vb[cur], eT);
        v = (Amk > 0.f) ? fmul2(s, ee) : v;
    }

    // partition_b = log( sum_c v[c] * exp(T[c,STOP]) ) + S   (in-warp only)
    float2 sp = g_stop2[lane];
    float term = lo2(v) * sp.x + hi2(v) * sp.y;
#pragma unroll
    for (int o = 16; o; o >>= 1) term += __shfl_xor_sync(0xffffffffu, term, o);
    if (lane == 0) g_part[b] = __logf(term) + S;
}

// ---------------------------------------------------------------------------
// Gold path score per batch (cheap gathers).
// ---------------------------------------------------------------------------
__global__ void __launch_bounds__(256) scores_kernel(const float* __restrict__ em,
                                                     const float* __restrict__ T,
                                                     const float* __restrict__ mask,
                                                     const int* __restrict__ tags) {
    const int b   = blockIdx.x;
    const int tid = threadIdx.x;
    const float* emb = em + (size_t)b * (LL * CC);
    const float* mkb = mask + (size_t)b * LL;
    const int*   tgb = tags + (size_t)b * LL;

    float acc = 0.f, msum = 0.f;
    for (int t = tid; t < LL; t += 256) {
        msum += mkb[t];
        if (t >= 1) {
            int tg = tgb[t];
            int tq = tgb[t - 1];
            acc += (emb[(size_t)t * CC + tg] + T[tq * CC + tg]) * mkb[t];
        }
    }

    __shared__ float sacc[8], smsum[8];
#pragma unroll
    for (int o = 16; o; o >>= 1) {
        acc  += __shfl_xor_sync(0xffffffffu, acc, o);
        msum += __shfl_xor_sync(0xffffffffu, msum, o);
    }
    int lane = tid & 31, w = tid >> 5;
    if (lane == 0) { sacc[w] = acc; smsum[w] = msum; }
    __syncthreads();
    if (tid == 0) {
        float A = 0.f, M = 0.f;
#pragma unroll
        for (int i = 0; i < 8; ++i) { A += sacc[i]; M += smsum[i]; }
        int t0 = tgb[0];
        float s = A + emb[t0] + T[START_S * CC + t0];
        int last = (int)M - 1;               // mask sum of 1.0s is exact in fp32
        s += T[tgb[last] * CC + STOP_S];
        g_scores[b] = s;
    }
}

// ---------------------------------------------------------------------------
// mean(partition - scores)
// ---------------------------------------------------------------------------
__global__ void __launch_bounds__(512) finalize_kernel(float* __restrict__ out) {
    int tid = threadIdx.x;
    float d = g_part[tid] - g_scores[tid];
    __shared__ float sh[16];
#pragma unroll
    for (int o = 16; o; o >>= 1) d += __shfl_xor_sync(0xffffffffu, d, o);
    if ((tid & 31) == 0) sh[tid >> 5] = d;
    __syncthreads();
    if (tid < 16) {
        float x = sh[tid];
#pragma unroll
        for (int o = 8; o; o >>= 1) x += __shfl_xor_sync(0x0000ffffu, x, o);
        if (tid == 0) out[0] = x * (1.0f / BB);
    }
}

extern "C" void kernel_launch(void* const* d_in, const int* in_sizes, int n_in,
                              void* d_out, int out_size) {
    (void)in_sizes; (void)n_in; (void)out_size;
    const float* em   = (const float*)d_in[0];
    const float* T    = (const float*)d_in[1];
    const float* mask = (const float*)d_in[2];
    const int*   tags = (const int*)d_in[3];
    float* out = (float*)d_out;

    prep_kernel<<<4, 512>>>(T);
    alpha_kernel<<<BB / 4, 128>>>(em, mask);
    scores_kernel<<<BB, 256>>>(em, T, mask, tags);
    finalize_kernel<<<1, 512>>>(out);
}